// round 6
// baseline (speedup 1.0000x reference)
#include <cuda_runtime.h>
#include <cstdint>

// EConv via per-launch CSR-by-dst build, then register-accumulate (no atomics
// in the 256MB-scale pass):
//   out[n,:] = sum_{e: dst[e]==n} x[src[e],:] * edge_attr[e,:]
// d_in[0]: x          float32 [100000*64]
// d_in[1]: edge_index int32   [2*1000000]  (row 0 = dst, row 1 = src)
// d_in[2]: edge_attr  float32 [1000000*64]
// d_out:   float32 [100000*64]
//
// Launch order: k_zero_off -> k_hist -> k_scan1 -> k_scan3 -> k_scatter -> k_econv

#define N_NODES 100000
#define E_MAX   1000000
#define D4      16          // float4 chunks per 64-float row
#define SCAN_B  1024
#define SCAN_NB ((N_NODES + 1 + SCAN_B - 1) / SCAN_B)   // 98

__device__ int  g_off[N_NODES + 1];   // counts -> scanned offsets
__device__ int  g_cur[N_NODES];       // scatter cursors
__device__ int2 g_es[E_MAX];          // {edge id, src} grouped by dst
__device__ int  g_part[SCAN_NB];      // per-block raw sums from scan1

__global__ void k_zero_off() {
    int i = blockIdx.x * blockDim.x + threadIdx.x;
    if (i <= N_NODES) g_off[i] = 0;
}

__global__ void k_hist(const int* __restrict__ dst, int E) {
    int e = blockIdx.x * blockDim.x + threadIdx.x;
    if (e < E) atomicAdd(&g_off[__ldcs(&dst[e]) + 1], 1);
}

// Inclusive scan within 1024-blocks; raw block totals to g_part.
__global__ __launch_bounds__(SCAN_B) void k_scan1() {
    __shared__ int warp_sums[32];
    int i = blockIdx.x * SCAN_B + threadIdx.x;
    int lane = threadIdx.x & 31, wid = threadIdx.x >> 5;
    int s = (i <= N_NODES) ? g_off[i] : 0;
#pragma unroll
    for (int d = 1; d < 32; d <<= 1) {
        int t = __shfl_up_sync(~0u, s, d);
        if (lane >= d) s += t;
    }
    if (lane == 31) warp_sums[wid] = s;
    __syncthreads();
    if (wid == 0) {
        int ws = warp_sums[lane];
#pragma unroll
        for (int d = 1; d < 32; d <<= 1) {
            int t = __shfl_up_sync(~0u, ws, d);
            if (lane >= d) ws += t;
        }
        warp_sums[lane] = ws;
    }
    __syncthreads();
    if (wid > 0) s += warp_sums[wid - 1];
    if (i <= N_NODES) g_off[i] = s;
    if (threadIdx.x == SCAN_B - 1) g_part[blockIdx.x] = s;
}

// Add cross-block prefix (computed inline from raw partials); init cursors.
__global__ __launch_bounds__(SCAN_B) void k_scan3() {
    __shared__ int warp_sums[32];
    __shared__ int s_off;
    int lane = threadIdx.x & 31, wid = threadIdx.x >> 5;

    // prefix = sum of g_part[j] for j < blockIdx.x  (<= 97 values)
    int acc = (threadIdx.x < blockIdx.x) ? g_part[threadIdx.x] : 0;
#pragma unroll
    for (int d = 16; d > 0; d >>= 1) acc += __shfl_down_sync(~0u, acc, d);
    if (lane == 0) warp_sums[wid] = acc;
    __syncthreads();
    if (wid == 0) {
        int v = (lane < SCAN_B / 32) ? warp_sums[lane] : 0;
#pragma unroll
        for (int d = 16; d > 0; d >>= 1) v += __shfl_down_sync(~0u, v, d);
        if (lane == 0) s_off = v;
    }
    __syncthreads();

    int i = blockIdx.x * SCAN_B + threadIdx.x;
    if (i > N_NODES) return;
    int v = g_off[i] + s_off;
    g_off[i] = v;
    if (i < N_NODES) g_cur[i] = v;
}

// Group edges by dst; store {e, src[e]} so the main loop has ONE index load.
__global__ void k_scatter(const int* __restrict__ dst,
                          const int* __restrict__ src, int E) {
    int e = blockIdx.x * blockDim.x + threadIdx.x;
    if (e < E) {
        int p = atomicAdd(&g_cur[__ldcs(&dst[e])], 1);
        g_es[p] = make_int2(e, __ldcs(&src[e]));
    }
}

// Warp per node. Lanes 0-15: even-k edges, lanes 16-31: odd-k edges.
// Each lane owns float4 chunk c = lane & 15. Combine halves via shuffle.
__global__ __launch_bounds__(256) void k_econv(
    const float4* __restrict__ x,        // [N, 16]
    const float4* __restrict__ attr,     // [E, 16]
    float4* __restrict__ out)            // [N, 16]
{
    int t = blockIdx.x * blockDim.x + threadIdx.x;
    int n = t >> 5;                      // node = warp
    if (n >= N_NODES) return;
    int lane = t & 31;
    int half = lane >> 4;                // 0 or 1
    int c = lane & 15;

    int k0 = __ldg(&g_off[n]);
    int k1 = __ldg(&g_off[n + 1]);

    float4 acc = make_float4(0.f, 0.f, 0.f, 0.f);

    int k = k0 + half;
    if (k < k1) {
        int2 es = __ldg(&g_es[k]);
        for (; k < k1; k += 2) {
            int2 es_n = es;
            if (k + 2 < k1) es_n = __ldg(&g_es[k + 2]);   // prefetch
            float4 av = __ldcs(&attr[(size_t)es.x * D4 + c]);
            float4 xv = __ldg(&x[(size_t)es.y * D4 + c]);
            acc.x = fmaf(av.x, xv.x, acc.x);
            acc.y = fmaf(av.y, xv.y, acc.y);
            acc.z = fmaf(av.z, xv.z, acc.z);
            acc.w = fmaf(av.w, xv.w, acc.w);
            es = es_n;
        }
    }

    // combine odd half into even half
    acc.x += __shfl_down_sync(~0u, acc.x, 16);
    acc.y += __shfl_down_sync(~0u, acc.y, 16);
    acc.z += __shfl_down_sync(~0u, acc.z, 16);
    acc.w += __shfl_down_sync(~0u, acc.w, 16);

    if (half == 0)
        out[(size_t)n * D4 + c] = acc;   // zeros for degree-0 nodes too
}

extern "C" void kernel_launch(void* const* d_in, const int* in_sizes, int n_in,
                              void* d_out, int out_size) {
    const float4* x = (const float4*)d_in[0];
    const int* edge_index = (const int*)d_in[1];
    const float4* edge_attr = (const float4*)d_in[2];

    int E = in_sizes[1] / 2;                 // 1,000,000
    const int* dst_idx = edge_index;         // row 0
    const int* src_idx = edge_index + E;     // row 1

    int nb_off = (N_NODES + 1 + 255) / 256;
    int nb_e   = (E + 255) / 256;

    k_zero_off<<<nb_off, 256>>>();
    k_hist<<<nb_e, 256>>>(dst_idx, E);
    k_scan1<<<SCAN_NB, SCAN_B>>>();
    k_scan3<<<SCAN_NB, SCAN_B>>>();
    k_scatter<<<nb_e, 256>>>(dst_idx, src_idx, E);

    long long total = (long long)N_NODES * 32;   // warp per node
    k_econv<<<(int)((total + 255) / 256), 256>>>(x, edge_attr, (float4*)d_out);
}

// round 7
// speedup vs baseline: 1.4577x; 1.4577x over previous
#include <cuda_runtime.h>
#include <cstdint>

// EConv: out[dst] += x[src] * edge_attr[e]  over 1M edges, d=64
// Edge-order processing (keeps the 256MB attr stream sequential),
// vectorized red.global.add.v4.f32 for accumulation.
// d_in[0]: x          float32 [100000*64]
// d_in[1]: edge_index int32   [2*1000000]  (row 0 = dst, row 1 = src)
// d_in[2]: edge_attr  float32 [1000000*64]
// d_out:   float32 [100000*64]

#define D 64
#define D4 (D / 4)   // 16 float4 chunks per row
#define EPT 4        // edges per thread

__global__ __launch_bounds__(256) void econv_kernel(
    const float4* __restrict__ x,          // [N, D/4]  (L2-resident, cached)
    const int* __restrict__ dst_idx,       // [E]       (streaming)
    const int* __restrict__ src_idx,       // [E]       (streaming)
    const float4* __restrict__ edge_attr,  // [E, D/4]  (streaming)
    float* __restrict__ out,               // [N, D]
    int E)
{
    int t = blockIdx.x * blockDim.x + threadIdx.x;
    int g = t >> 4;          // edge-group id
    int c = t & 15;          // float4 chunk within the 64-wide row
    int e0 = g * EPT;
    if (e0 >= E) return;

    // One LDG.128 each for 4 src + 4 dst indices (e0 is 4-aligned)
    int4 s4 = __ldcs((const int4*)(src_idx + e0));
    int4 d4 = __ldcs((const int4*)(dst_idx + e0));
    int src[EPT] = {s4.x, s4.y, s4.z, s4.w};
    int dst[EPT] = {d4.x, d4.y, d4.z, d4.w};

    // Front-batch the 8 data loads for MLP; x cached (L2), attr evict-first
    float4 xv[EPT], av[EPT];
#pragma unroll
    for (int i = 0; i < EPT; i++) {
        xv[i] = __ldg(&x[(size_t)src[i] * D4 + c]);
        av[i] = __ldcs(&edge_attr[(size_t)(e0 + i) * D4 + c]);
    }

#pragma unroll
    for (int i = 0; i < EPT; i++) {
        av[i].x *= xv[i].x;
        av[i].y *= xv[i].y;
        av[i].z *= xv[i].z;
        av[i].w *= xv[i].w;
        float* p = out + (size_t)dst[i] * D + c * 4;
        asm volatile(
            "red.global.add.v4.f32 [%0], {%1, %2, %3, %4};"
            :: "l"(p), "f"(av[i].x), "f"(av[i].y), "f"(av[i].z), "f"(av[i].w)
            : "memory");
    }
}

extern "C" void kernel_launch(void* const* d_in, const int* in_sizes, int n_in,
                              void* d_out, int out_size) {
    const float4* x = (const float4*)d_in[0];
    const int* edge_index = (const int*)d_in[1];
    const float4* edge_attr = (const float4*)d_in[2];

    int E = in_sizes[1] / 2;                 // 1,000,000
    const int* dst_idx = edge_index;         // row 0
    const int* src_idx = edge_index + E;     // row 1

    // Zero the output via a memset node (graph-capturable, cheaper than a kernel)
    cudaMemsetAsync(d_out, 0, (size_t)out_size * sizeof(float));

    long long total = (long long)(E / EPT) * 16;  // 4M threads (E divisible by 4)
    int blocks = (int)((total + 255) / 256);
    econv_kernel<<<blocks, 256>>>(
        x, dst_idx, src_idx, edge_attr, (float*)d_out, E);
}

// round 8
// speedup vs baseline: 1.4690x; 1.0078x over previous
#include <cuda_runtime.h>
#include <cstdint>

// EConv: out[dst] += x[src] * edge_attr[e]  over 1M edges, d=64
// Edge-order, vectorized red.global.add.v4.f32; 32-bit offset arithmetic.
// d_in[0]: x          float32 [100000*64]
// d_in[1]: edge_index int32   [2*1000000]  (row 0 = dst, row 1 = src)
// d_in[2]: edge_attr  float32 [1000000*64]
// d_out:   float32 [100000*64]

#define D 64
#define ROW_BYTES 256u   // 64 floats
#define EPT 4            // edges per thread

__global__ __launch_bounds__(512) void econv_kernel(
    const char* __restrict__ x_b,         // x base (bytes)
    const int* __restrict__ dst_idx,      // [E]
    const int* __restrict__ src_idx,      // [E]
    const char* __restrict__ attr_b,      // edge_attr base (bytes)
    char* __restrict__ out_b,             // out base (bytes)
    int E)
{
    int t = blockIdx.x * blockDim.x + threadIdx.x;
    int g = t >> 4;              // edge-group id
    unsigned cb = (t & 15) * 16u; // byte offset of this thread's float4 chunk
    int e0 = g * EPT;
    if (e0 >= E) return;

    // One LDG.128 each for 4 src + 4 dst indices (e0 is 4-aligned)
    int4 s4 = __ldcs((const int4*)(src_idx + e0));
    int4 d4 = __ldcs((const int4*)(dst_idx + e0));
    int src[EPT] = {s4.x, s4.y, s4.z, s4.w};
    int dst[EPT] = {d4.x, d4.y, d4.z, d4.w};

    // Front-batch the 8 data loads (32-bit offsets: all arrays < 4GB)
    float4 xv[EPT], av[EPT];
    unsigned ab = (unsigned)e0 * ROW_BYTES + cb;
#pragma unroll
    for (int i = 0; i < EPT; i++) {
        xv[i] = __ldg((const float4*)(x_b + ((unsigned)src[i] * ROW_BYTES + cb)));
        av[i] = __ldcs((const float4*)(attr_b + ab + (unsigned)i * ROW_BYTES));
    }

#pragma unroll
    for (int i = 0; i < EPT; i++) {
        av[i].x *= xv[i].x;
        av[i].y *= xv[i].y;
        av[i].z *= xv[i].z;
        av[i].w *= xv[i].w;
        char* p = out_b + ((unsigned)dst[i] * ROW_BYTES + cb);
        asm volatile(
            "red.global.add.v4.f32 [%0], {%1, %2, %3, %4};"
            :: "l"(p), "f"(av[i].x), "f"(av[i].y), "f"(av[i].z), "f"(av[i].w)
            : "memory");
    }
}

extern "C" void kernel_launch(void* const* d_in, const int* in_sizes, int n_in,
                              void* d_out, int out_size) {
    const char* x_b = (const char*)d_in[0];
    const int* edge_index = (const int*)d_in[1];
    const char* attr_b = (const char*)d_in[2];

    int E = in_sizes[1] / 2;                 // 1,000,000
    const int* dst_idx = edge_index;         // row 0
    const int* src_idx = edge_index + E;     // row 1

    // Zero the output via a memset node
    cudaMemsetAsync(d_out, 0, (size_t)out_size * sizeof(float));

    long long total = (long long)(E / EPT) * 16;  // 4M threads
    int blocks = (int)((total + 511) / 512);
    econv_kernel<<<blocks, 512>>>(
        x_b, dst_idx, src_idx, attr_b, (char*)d_out, E);
}